// round 14
// baseline (speedup 1.0000x reference)
#include <cuda_runtime.h>
#include <cuda_bf16.h>
#include <math.h>

#define BB 4
#define C 128
#define H 256
#define W 256
#define HW (H*W)

// K1: per batch: 4096 H-blocks then 1024 V-blocks (L2 x-reuse at batch granularity)
#define BLKS_PER_B (C*(H/8) + C*8)     // 5120
#define GRID_K1 (BB*BLKS_PER_B)        // 20480

// ---------------- scratch (device globals; no allocations allowed) ----------------
__device__ __align__(16) __nv_bfloat16 g_h[(size_t)BB*C*HW];   // 64 MB
__device__ __align__(16) __nv_bfloat16 g_v[(size_t)BB*C*HW];   // 64 MB
__device__ __align__(16) __nv_bfloat16 g_fwb[C*C];
__device__ float g_hpart[BB*C*32];
__device__ float g_vpart[BB*C*32];
__device__ float g_gate[BB*2];

// ---------------- K1: both directional two-stage convs, per-batch H->V --------------
__global__ void __launch_bounds__(256) k1_conv(const float* __restrict__ x,
                                               const float* __restrict__ h1w,
                                               const float* __restrict__ h2w,
                                               const float* __restrict__ v1w,
                                               const float* __restrict__ v2w) {
    int blk = blockIdx.x;
    int t = threadIdx.x;
    __shared__ float ssum[8];
    float thread_sum;
    int partIdx;

    int batch = blk / BLKS_PER_B;
    int sub = blk - batch*BLKS_PER_B;
    bool isH = (sub < C*(H/8));

    if (isH) {
        int rowblk = sub & 31;
        int bc = batch*C + (sub >> 5);
        int c = bc & (C - 1);
        int warp = t >> 5, lane = t & 31;
        int row = rowblk*8 + warp;
        const float* xr = x + (size_t)bc*HW + (size_t)row*W;
        int p0 = lane * 8;

        float w1[5], w2[7];
        #pragma unroll
        for (int i = 0; i < 5; i++) w1[i] = h1w[c*5 + i];
        #pragma unroll
        for (int j = 0; j < 7; j++) w2[j] = h2w[c*7 + j];

        int bl = p0 - 4;
        float4 c0 = *(const float4*)(xr + (bl < 0 ? 0 : bl));
        float4 c1 = *(const float4*)(xr + p0);
        float4 c1b = *(const float4*)(xr + p0 + 4);
        int br = p0 + 8;
        float4 c2 = *(const float4*)(xr + (br > W-4 ? W-4 : br));
        float wq[12];
        wq[0] = (lane > 0) ? c0.z : 0.f;
        wq[1] = (lane > 0) ? c0.w : 0.f;
        wq[2] = c1.x; wq[3] = c1.y; wq[4] = c1.z; wq[5] = c1.w;
        wq[6] = c1b.x; wq[7] = c1b.y; wq[8] = c1b.z; wq[9] = c1b.w;
        wq[10] = (lane < 31) ? c2.x : 0.f;
        wq[11] = (lane < 31) ? c2.y : 0.f;

        float s1[8];
        #pragma unroll
        for (int k = 0; k < 8; k++) {
            float s = 0.f;
            #pragma unroll
            for (int i = 0; i < 5; i++) s = fmaf(w1[i], wq[k + i], s);
            s1[k] = s;
        }

        float wf[26];
        {
            float vv = __shfl_up_sync(0xffffffffu, s1[7], 2);
            wf[0] = (lane >= 2) ? vv : 0.f;
        }
        #pragma unroll
        for (int k = 0; k < 8; k++) {
            float vv = __shfl_up_sync(0xffffffffu, s1[k], 1);
            wf[1 + k] = (lane >= 1) ? vv : 0.f;
        }
        #pragma unroll
        for (int k = 0; k < 8; k++) wf[9 + k] = s1[k];
        #pragma unroll
        for (int k = 0; k < 8; k++) {
            float vv = __shfl_down_sync(0xffffffffu, s1[k], 1);
            wf[17 + k] = (lane <= 30) ? vv : 0.f;
        }
        {
            float vv = __shfl_down_sync(0xffffffffu, s1[0], 2);
            wf[25] = (lane <= 29) ? vv : 0.f;
        }

        __nv_bfloat16 ob[8];
        thread_sum = 0.f;
        #pragma unroll
        for (int d = 0; d < 8; d++) {
            float a = 0.f;
            #pragma unroll
            for (int j = 0; j < 7; j++) a = fmaf(w2[j], wf[d + 3*j], a);
            thread_sum += a;
            ob[d] = __float2bfloat16(a);
        }
        *(uint4*)(g_h + (size_t)bc*HW + (size_t)row*W + p0) = *(uint4*)ob;
        partIdx = bc*32 + rowblk;
    } else {
        int sub2 = sub - C*(H/8);
        int xt = sub2 & 1;
        int yt = (sub2 >> 1) & 3;
        int bc = batch*C + (sub2 >> 3);
        int c = bc & (C - 1);
        int tx = t & 127, ty = t >> 7;
        int col = xt*128 + tx;
        int y0 = yt*64 + ty*32;
        const float* xc = x + (size_t)bc*HW + col;

        float w1[5], w2[7];
        #pragma unroll
        for (int i = 0; i < 5; i++) w1[i] = v1w[c*5 + i];
        #pragma unroll
        for (int j = 0; j < 7; j++) w2[j] = v2w[c*7 + j];

        float acc[32];
        #pragma unroll
        for (int d = 0; d < 32; d++) acc[d] = 0.f;

        float xr[5];
        #pragma unroll
        for (int m = 0; m < 4; m++) {
            int gy = y0 - 11 + m;
            xr[m] = (gy >= 0 && gy < H) ? xc[gy*W] : 0.f;
        }
        #pragma unroll
        for (int k = 0; k < 50; k++) {
            int gy = y0 - 7 + k;
            xr[(k + 4) % 5] = (gy >= 0 && gy < H) ? xc[gy*W] : 0.f;
            float s = 0.f;
            #pragma unroll
            for (int i = 0; i < 5; i++) s = fmaf(w1[i], xr[(k + i) % 5], s);
            int gy1 = y0 - 9 + k;
            s = (gy1 >= 0 && gy1 < H) ? s : 0.f;
            #pragma unroll
            for (int j = 0; j < 7; j++) {
                int d = k - 3*j;
                if (d >= 0 && d < 32) acc[d] = fmaf(w2[j], s, acc[d]);
            }
        }
        __nv_bfloat16* vpb = g_v + (size_t)bc*HW + col;
        thread_sum = 0.f;
        #pragma unroll
        for (int d = 0; d < 32; d++) {
            vpb[(y0 + d)*W] = __float2bfloat16(acc[d]);
            thread_sum += acc[d];
        }
        partIdx = bc*32 + (yt*2 + xt);
    }

    float s = thread_sum;
    #pragma unroll
    for (int off = 16; off; off >>= 1) s += __shfl_down_sync(0xffffffffu, s, off);
    if ((t & 31) == 0) ssum[t >> 5] = s;
    __syncthreads();
    if (t == 0) {
        float tot = 0.f;
        #pragma unroll
        for (int i = 0; i < 8; i++) tot += ssum[i];
        if (isH) g_hpart[partIdx] = tot;
        else     g_vpart[partIdx] = tot;
    }
}

// ---------------- K2: gate MLP + softmax + fw->bf16 conversion -----------------------
__global__ void __launch_bounds__(512) k2_gate(const float* __restrict__ g1,
                                               const float* __restrict__ g2,
                                               const float* __restrict__ g2b,
                                               const float* __restrict__ fw) {
    __shared__ float shs[BB*C];
    __shared__ float svs[BB*C];
    __shared__ float sp[BB][32][4];
    __shared__ float sg[BB][32];
    __shared__ float sl[BB][2];
    int t = threadIdx.x;

    for (int i = t; i < C*C; i += 512) g_fwb[i] = __float2bfloat16(fw[i]);

    {
        int bc = t;
        float s = 0.f;
        #pragma unroll 8
        for (int i = 0; i < 32; i++) s += g_hpart[bc*32 + i];
        shs[bc] = s;
        s = 0.f;
        #pragma unroll
        for (int i = 0; i < 8; i++) s += g_vpart[bc*32 + i];
        svs[bc] = s;
    }
    __syncthreads();
    {
        int b = t >> 7, k = (t >> 2) & 31, c4 = t & 3;
        const float inv = 1.f / 65536.f;
        float acc = 0.f;
        int cc0 = c4 * 64;
        #pragma unroll 8
        for (int cc = cc0; cc < cc0 + 64; cc++) {
            float p = (cc < C ? shs[b*C + cc] : svs[b*C + cc - C]) * inv;
            acc = fmaf(p, g1[k*(2*C) + cc], acc);
        }
        sp[b][k][c4] = acc;
    }
    __syncthreads();
    if (t < BB*32) {
        int b = t >> 5, k = t & 31;
        float g = sp[b][k][0] + sp[b][k][1] + sp[b][k][2] + sp[b][k][3];
        float sig = 1.f / (1.f + expf(-g));
        sg[b][k] = g * sig;
    }
    __syncthreads();
    if (t < BB*2) {
        int b = t >> 1, j = t & 1;
        float acc = g2b[j];
        #pragma unroll
        for (int k = 0; k < 32; k++) acc = fmaf(sg[b][k], g2[j*32 + k], acc);
        sl[b][j] = acc;
    }
    __syncthreads();
    if (t < BB) {
        float a = sl[t][0], b2 = sl[t][1];
        float m = fmaxf(a, b2);
        float e0 = expf(a - m), e1 = expf(b2 - m);
        float inv = 1.f / (e0 + e1);
        g_gate[t*2 + 0] = e0 * inv;
        g_gate[t*2 + 1] = e1 * inv;
    }
}

// ---------------- K3: persistent split-GEMM, 64-px tiles, 3-stage pipeline -----------
#define SFW_STRIDE 136                   // bf16 elems per row (272B)
#define SB_STRIDE  72                    // bf16 elems per row (144B)
#define SB_BYTES   (128*SB_STRIDE*2)     // 18432
#define SX_STRIDE  72                    // floats per row (288B)
#define SX_BYTES   (128*SX_STRIDE*4)     // 36864
#define STAGE_BYTES (2*SB_BYTES + SX_BYTES)  // 73728: H + V + X
#define NSTAGE 3
#define K3_SMEM    (NSTAGE*STAGE_BYTES)  // 221184
#define NB3 152
#define NTILES (BB*(HW/64))              // 4096

__device__ __forceinline__ void cpa16(unsigned dst, const void* src) {
    asm volatile("cp.async.cg.shared.global [%0], [%1], 16;" :: "r"(dst), "l"(src));
}
__device__ __forceinline__ void ldsm_x4(unsigned addr, unsigned &r0, unsigned &r1,
                                        unsigned &r2, unsigned &r3) {
    asm volatile("ldmatrix.sync.aligned.m8n8.x4.shared.b16 {%0,%1,%2,%3}, [%4];"
                 : "=r"(r0), "=r"(r1), "=r"(r2), "=r"(r3) : "r"(addr));
}
__device__ __forceinline__ void ldsm_x4t(unsigned addr, unsigned &r0, unsigned &r1,
                                         unsigned &r2, unsigned &r3) {
    asm volatile("ldmatrix.sync.aligned.m8n8.x4.trans.shared.b16 {%0,%1,%2,%3}, [%4];"
                 : "=r"(r0), "=r"(r1), "=r"(r2), "=r"(r3) : "r"(addr));
}
__device__ __forceinline__ void mma16816(float* d, const unsigned* a,
                                         unsigned b0, unsigned b1) {
    asm volatile("mma.sync.aligned.m16n8k16.row.col.f32.bf16.bf16.f32 "
                 "{%0,%1,%2,%3}, {%4,%5,%6,%7}, {%8,%9}, {%0,%1,%2,%3};"
                 : "+f"(d[0]), "+f"(d[1]), "+f"(d[2]), "+f"(d[3])
                 : "r"(a[0]), "r"(a[1]), "r"(a[2]), "r"(a[3]), "r"(b0), "r"(b1));
}

__device__ __forceinline__ void k3_stage(unsigned su, int tile, int t,
                                         const float* __restrict__ x) {
    int b = tile >> 10;
    int p0 = (tile & 1023) * 64;
    #pragma unroll
    for (int rep = 0; rep < 4; rep++) {
        int idx = t + rep*256;
        int cc = idx >> 3, q = idx & 7;
        size_t gi = ((size_t)(b*C + cc))*HW + p0 + q*8;
        unsigned doff = cc*(SB_STRIDE*2) + q*16;
        cpa16(su + doff, g_h + gi);
        cpa16(su + SB_BYTES + doff, g_v + gi);
    }
    #pragma unroll
    for (int rep = 0; rep < 8; rep++) {
        int idx = t + rep*256;
        int cc = idx >> 4, q = idx & 15;
        size_t gi = ((size_t)(b*C + cc))*HW + p0 + q*4;
        cpa16(su + 2*SB_BYTES + cc*(SX_STRIDE*4) + q*16, x + gi);
    }
}

__global__ void __launch_bounds__(256, 1) k3_fuse(const float* __restrict__ x,
                                                  const float* __restrict__ fb,
                                                  float* __restrict__ out) {
    extern __shared__ __align__(16) char sm3[];
    unsigned st0u = (unsigned)__cvta_generic_to_shared(sm3);
    int t = threadIdx.x;
    int w = t >> 5, l = t & 31;

    int aRow = 16*w + (l & 15);
    int aColHalf = (l >> 4) * 8;
    int bRowLocal = (l & 7) + (((l >> 3) & 1) << 3);
    int bColHalf = (l >> 4) * 8;
    int r0 = 16*w + (l >> 2);

    // ---- prologue: stage fw into buf0, hoist A fragments to registers ----
    #pragma unroll
    for (int rep = 0; rep < 8; rep++) {
        int idx = t + rep*256;
        int row = idx >> 4, cq = idx & 15;
        cpa16(st0u + row*(SFW_STRIDE*2) + cq*16, g_fwb + row*128 + cq*8);
    }
    asm volatile("cp.async.commit_group;");
    asm volatile("cp.async.wait_group 0;");
    __syncthreads();
    unsigned afr[8][4];
    #pragma unroll
    for (int kk = 0; kk < 8; kk++) {
        unsigned aAddr = st0u + (unsigned)(aRow*SFW_STRIDE + kk*16 + aColHalf)*2u;
        ldsm_x4(aAddr, afr[kk][0], afr[kk][1], afr[kk][2], afr[kk][3]);
    }
    __syncthreads();   // all warps done with fw region before overwrite

    int tile = blockIdx.x;
    if (tile < NTILES) k3_stage(st0u, tile, t, x);
    asm volatile("cp.async.commit_group;");
    if (tile + NB3 < NTILES) k3_stage(st0u + STAGE_BYTES, tile + NB3, t, x);
    asm volatile("cp.async.commit_group;");

    float fb0 = fb[r0], fb1 = fb[r0 + 8];
    int bufc = 0;                         // buffer of current tile
    int bufn = 2;                         // buffer for tile+2

    for (; tile < NTILES; tile += NB3) {
        // stage tile+2 into its buffer (prev consumers finished last iteration)
        int stile = tile + 2*NB3;
        if (stile < NTILES) k3_stage(st0u + bufn*STAGE_BYTES, stile, t, x);
        asm volatile("cp.async.commit_group;");
        asm volatile("cp.async.wait_group 2;");   // current tile complete
        __syncthreads();

        unsigned cur = st0u + bufc*STAGE_BYTES;
        int b = tile >> 10;
        int p0 = (tile & 1023) * 64;
        float wh = g_gate[b*2 + 0], wv = g_gate[b*2 + 1];
        unsigned sHu = cur, sVu = cur + SB_BYTES;
        const char* sX = sm3 + (size_t)bufc*STAGE_BYTES + 2*SB_BYTES;

        float accH[8][4], accV[8][4];
        #pragma unroll
        for (int n = 0; n < 8; n++)
            #pragma unroll
            for (int i = 0; i < 4; i++) { accH[n][i] = 0.f; accV[n][i] = 0.f; }

        #pragma unroll
        for (int kk = 0; kk < 8; kk++) {
            #pragma unroll
            for (int nn = 0; nn < 4; nn++) {
                unsigned boff = (unsigned)((kk*16 + bRowLocal)*SB_STRIDE
                                           + nn*16 + bColHalf)*2u;
                unsigned b0, b1, b2, b3;
                ldsm_x4t(sHu + boff, b0, b1, b2, b3);
                mma16816(accH[2*nn],     afr[kk], b0, b1);
                mma16816(accH[2*nn + 1], afr[kk], b2, b3);
                ldsm_x4t(sVu + boff, b0, b1, b2, b3);
                mma16816(accV[2*nn],     afr[kk], b0, b1);
                mma16816(accV[2*nn + 1], afr[kk], b2, b3);
            }
        }

        int pxl = 2*(l & 3);
        #pragma unroll
        for (int nt = 0; nt < 8; nt++) {
            int px = pxl + nt*8;
            float2 xv0 = *(const float2*)(sX + r0*(SX_STRIDE*4) + px*4);
            float a0 = fmaf(wh, accH[nt][0], wv * accV[nt][0]);
            float a1 = fmaf(wh, accH[nt][1], wv * accV[nt][1]);
            float2 o0;
            o0.x = xv0.x * (0.5f + 0.5f*(a0 + fb0));
            o0.y = xv0.y * (0.5f + 0.5f*(a1 + fb0));
            size_t base0 = ((size_t)(b*C + r0))*HW + p0 + px;
            *(float2*)(out + base0) = o0;
            float2 xv1 = *(const float2*)(sX + (r0 + 8)*(SX_STRIDE*4) + px*4);
            float a2 = fmaf(wh, accH[nt][2], wv * accV[nt][2]);
            float a3 = fmaf(wh, accH[nt][3], wv * accV[nt][3]);
            float2 o1;
            o1.x = xv1.x * (0.5f + 0.5f*(a2 + fb1));
            o1.y = xv1.y * (0.5f + 0.5f*(a3 + fb1));
            *(float2*)(out + base0 + (size_t)8*HW) = o1;
        }
        __syncthreads();   // cur readers done before it's restaged in 2 iterations

        bufc = (bufc == 2) ? 0 : bufc + 1;
        bufn = (bufn == 2) ? 0 : bufn + 1;
    }
}

// ---------------- launch -------------------------------------------------------------
extern "C" void kernel_launch(void* const* d_in, const int* in_sizes, int n_in,
                              void* d_out, int out_size) {
    const float* x   = (const float*)d_in[0];
    const float* h1  = (const float*)d_in[1];
    const float* h2  = (const float*)d_in[2];
    const float* v1  = (const float*)d_in[3];
    const float* v2  = (const float*)d_in[4];
    const float* g1  = (const float*)d_in[5];
    const float* g2  = (const float*)d_in[6];
    const float* g2b = (const float*)d_in[7];
    const float* fw  = (const float*)d_in[8];
    const float* fb  = (const float*)d_in[9];
    float* out = (float*)d_out;

    static int smem_set = 0;
    if (!smem_set) {
        cudaFuncSetAttribute(k3_fuse, cudaFuncAttributeMaxDynamicSharedMemorySize,
                             K3_SMEM);
        smem_set = 1;
    }

    k1_conv<<<GRID_K1, 256>>>(x, h1, h2, v1, v2);
    k2_gate<<<1, 512>>>(g1, g2, g2b, fw);
    k3_fuse<<<NB3, 256, K3_SMEM>>>(x, fb, out);
}

// round 15
// speedup vs baseline: 1.0885x; 1.0885x over previous
#include <cuda_runtime.h>
#include <cuda_bf16.h>
#include <math.h>

#define BB 4
#define C 128
#define H 256
#define W 256
#define HW (H*W)

// K1: per batch: 4096 H-blocks then 1024 V-blocks (L2 x-reuse at batch granularity)
#define BLKS_PER_B (C*(H/8) + C*8)     // 5120
#define GRID_K1 (BB*BLKS_PER_B)        // 20480

// ---------------- scratch (device globals; no allocations allowed) ----------------
__device__ __align__(16) __nv_bfloat16 g_h[(size_t)BB*C*HW];   // 64 MB
__device__ __align__(16) __nv_bfloat16 g_v[(size_t)BB*C*HW];   // 64 MB
__device__ __align__(16) __nv_bfloat16 g_fwb[C*C];
__device__ float g_hpart[BB*C*32];
__device__ float g_vpart[BB*C*32];
__device__ float g_gate[BB*2];

// ---------------- K1: both directional two-stage convs, per-batch H->V --------------
__global__ void __launch_bounds__(256) k1_conv(const float* __restrict__ x,
                                               const float* __restrict__ h1w,
                                               const float* __restrict__ h2w,
                                               const float* __restrict__ v1w,
                                               const float* __restrict__ v2w) {
    int blk = blockIdx.x;
    int t = threadIdx.x;
    __shared__ float ssum[8];
    float thread_sum;
    int partIdx;

    int batch = blk / BLKS_PER_B;
    int sub = blk - batch*BLKS_PER_B;
    bool isH = (sub < C*(H/8));

    if (isH) {
        int rowblk = sub & 31;
        int bc = batch*C + (sub >> 5);
        int c = bc & (C - 1);
        int warp = t >> 5, lane = t & 31;
        int row = rowblk*8 + warp;
        const float* xr = x + (size_t)bc*HW + (size_t)row*W;
        int p0 = lane * 8;

        float w1[5], w2[7];
        #pragma unroll
        for (int i = 0; i < 5; i++) w1[i] = h1w[c*5 + i];
        #pragma unroll
        for (int j = 0; j < 7; j++) w2[j] = h2w[c*7 + j];

        int bl = p0 - 4;
        float4 c0 = *(const float4*)(xr + (bl < 0 ? 0 : bl));
        float4 c1 = *(const float4*)(xr + p0);
        float4 c1b = *(const float4*)(xr + p0 + 4);
        int br = p0 + 8;
        float4 c2 = *(const float4*)(xr + (br > W-4 ? W-4 : br));
        float wq[12];
        wq[0] = (lane > 0) ? c0.z : 0.f;
        wq[1] = (lane > 0) ? c0.w : 0.f;
        wq[2] = c1.x; wq[3] = c1.y; wq[4] = c1.z; wq[5] = c1.w;
        wq[6] = c1b.x; wq[7] = c1b.y; wq[8] = c1b.z; wq[9] = c1b.w;
        wq[10] = (lane < 31) ? c2.x : 0.f;
        wq[11] = (lane < 31) ? c2.y : 0.f;

        float s1[8];
        #pragma unroll
        for (int k = 0; k < 8; k++) {
            float s = 0.f;
            #pragma unroll
            for (int i = 0; i < 5; i++) s = fmaf(w1[i], wq[k + i], s);
            s1[k] = s;
        }

        float wf[26];
        {
            float vv = __shfl_up_sync(0xffffffffu, s1[7], 2);
            wf[0] = (lane >= 2) ? vv : 0.f;
        }
        #pragma unroll
        for (int k = 0; k < 8; k++) {
            float vv = __shfl_up_sync(0xffffffffu, s1[k], 1);
            wf[1 + k] = (lane >= 1) ? vv : 0.f;
        }
        #pragma unroll
        for (int k = 0; k < 8; k++) wf[9 + k] = s1[k];
        #pragma unroll
        for (int k = 0; k < 8; k++) {
            float vv = __shfl_down_sync(0xffffffffu, s1[k], 1);
            wf[17 + k] = (lane <= 30) ? vv : 0.f;
        }
        {
            float vv = __shfl_down_sync(0xffffffffu, s1[0], 2);
            wf[25] = (lane <= 29) ? vv : 0.f;
        }

        __nv_bfloat16 ob[8];
        thread_sum = 0.f;
        #pragma unroll
        for (int d = 0; d < 8; d++) {
            float a = 0.f;
            #pragma unroll
            for (int j = 0; j < 7; j++) a = fmaf(w2[j], wf[d + 3*j], a);
            thread_sum += a;
            ob[d] = __float2bfloat16(a);
        }
        *(uint4*)(g_h + (size_t)bc*HW + (size_t)row*W + p0) = *(uint4*)ob;
        partIdx = bc*32 + rowblk;
    } else {
        int sub2 = sub - C*(H/8);
        int xt = sub2 & 1;
        int yt = (sub2 >> 1) & 3;
        int bc = batch*C + (sub2 >> 3);
        int c = bc & (C - 1);
        int tx = t & 127, ty = t >> 7;
        int col = xt*128 + tx;
        int y0 = yt*64 + ty*32;
        const float* xc = x + (size_t)bc*HW + col;

        float w1[5], w2[7];
        #pragma unroll
        for (int i = 0; i < 5; i++) w1[i] = v1w[c*5 + i];
        #pragma unroll
        for (int j = 0; j < 7; j++) w2[j] = v2w[c*7 + j];

        float acc[32];
        #pragma unroll
        for (int d = 0; d < 32; d++) acc[d] = 0.f;

        float xr[5];
        #pragma unroll
        for (int m = 0; m < 4; m++) {
            int gy = y0 - 11 + m;
            xr[m] = (gy >= 0 && gy < H) ? xc[gy*W] : 0.f;
        }
        #pragma unroll
        for (int k = 0; k < 50; k++) {
            int gy = y0 - 7 + k;
            xr[(k + 4) % 5] = (gy >= 0 && gy < H) ? xc[gy*W] : 0.f;
            float s = 0.f;
            #pragma unroll
            for (int i = 0; i < 5; i++) s = fmaf(w1[i], xr[(k + i) % 5], s);
            int gy1 = y0 - 9 + k;
            s = (gy1 >= 0 && gy1 < H) ? s : 0.f;
            #pragma unroll
            for (int j = 0; j < 7; j++) {
                int d = k - 3*j;
                if (d >= 0 && d < 32) acc[d] = fmaf(w2[j], s, acc[d]);
            }
        }
        __nv_bfloat16* vpb = g_v + (size_t)bc*HW + col;
        thread_sum = 0.f;
        #pragma unroll
        for (int d = 0; d < 32; d++) {
            vpb[(y0 + d)*W] = __float2bfloat16(acc[d]);
            thread_sum += acc[d];
        }
        partIdx = bc*32 + (yt*2 + xt);
    }

    float s = thread_sum;
    #pragma unroll
    for (int off = 16; off; off >>= 1) s += __shfl_down_sync(0xffffffffu, s, off);
    if ((t & 31) == 0) ssum[t >> 5] = s;
    __syncthreads();
    if (t == 0) {
        float tot = 0.f;
        #pragma unroll
        for (int i = 0; i < 8; i++) tot += ssum[i];
        if (isH) g_hpart[partIdx] = tot;
        else     g_vpart[partIdx] = tot;
    }
}

// ---------------- K2: gate MLP + softmax + fw->bf16 conversion -----------------------
__global__ void __launch_bounds__(512) k2_gate(const float* __restrict__ g1,
                                               const float* __restrict__ g2,
                                               const float* __restrict__ g2b,
                                               const float* __restrict__ fw) {
    __shared__ float shs[BB*C];
    __shared__ float svs[BB*C];
    __shared__ float sp[BB][32][4];
    __shared__ float sg[BB][32];
    __shared__ float sl[BB][2];
    int t = threadIdx.x;

    for (int i = t; i < C*C; i += 512) g_fwb[i] = __float2bfloat16(fw[i]);

    {
        int bc = t;
        float s = 0.f;
        #pragma unroll 8
        for (int i = 0; i < 32; i++) s += g_hpart[bc*32 + i];
        shs[bc] = s;
        s = 0.f;
        #pragma unroll
        for (int i = 0; i < 8; i++) s += g_vpart[bc*32 + i];
        svs[bc] = s;
    }
    __syncthreads();
    {
        int b = t >> 7, k = (t >> 2) & 31, c4 = t & 3;
        const float inv = 1.f / 65536.f;
        float acc = 0.f;
        int cc0 = c4 * 64;
        #pragma unroll 8
        for (int cc = cc0; cc < cc0 + 64; cc++) {
            float p = (cc < C ? shs[b*C + cc] : svs[b*C + cc - C]) * inv;
            acc = fmaf(p, g1[k*(2*C) + cc], acc);
        }
        sp[b][k][c4] = acc;
    }
    __syncthreads();
    if (t < BB*32) {
        int b = t >> 5, k = t & 31;
        float g = sp[b][k][0] + sp[b][k][1] + sp[b][k][2] + sp[b][k][3];
        float sig = 1.f / (1.f + expf(-g));
        sg[b][k] = g * sig;
    }
    __syncthreads();
    if (t < BB*2) {
        int b = t >> 1, j = t & 1;
        float acc = g2b[j];
        #pragma unroll
        for (int k = 0; k < 32; k++) acc = fmaf(sg[b][k], g2[j*32 + k], acc);
        sl[b][j] = acc;
    }
    __syncthreads();
    if (t < BB) {
        float a = sl[t][0], b2 = sl[t][1];
        float m = fmaxf(a, b2);
        float e0 = expf(a - m), e1 = expf(b2 - m);
        float inv = 1.f / (e0 + e1);
        g_gate[t*2 + 0] = e0 * inv;
        g_gate[t*2 + 1] = e1 * inv;
    }
}

// ---------------- K3: persistent split-GEMM, 64-px tiles, 4x2 warp tiling ------------
#define SFW_STRIDE 136                   // bf16 elems per row (272B)
#define SB_STRIDE  72                    // bf16 elems per row (144B)
#define SB_BYTES   (128*SB_STRIDE*2)     // 18432
#define SX_STRIDE  72                    // floats per row (288B)
#define SX_BYTES   (128*SX_STRIDE*4)     // 36864
#define STAGE_BYTES (2*SB_BYTES + SX_BYTES)  // 73728: H + V + X
#define K3_SMEM    (2*STAGE_BYTES)       // 147456
#define NB3 152
#define NTILES (BB*(HW/64))              // 4096

__device__ __forceinline__ void cpa16(unsigned dst, const void* src) {
    asm volatile("cp.async.cg.shared.global [%0], [%1], 16;" :: "r"(dst), "l"(src));
}
__device__ __forceinline__ void ldsm_x4(unsigned addr, unsigned &r0, unsigned &r1,
                                        unsigned &r2, unsigned &r3) {
    asm volatile("ldmatrix.sync.aligned.m8n8.x4.shared.b16 {%0,%1,%2,%3}, [%4];"
                 : "=r"(r0), "=r"(r1), "=r"(r2), "=r"(r3) : "r"(addr));
}
__device__ __forceinline__ void ldsm_x4t(unsigned addr, unsigned &r0, unsigned &r1,
                                         unsigned &r2, unsigned &r3) {
    asm volatile("ldmatrix.sync.aligned.m8n8.x4.trans.shared.b16 {%0,%1,%2,%3}, [%4];"
                 : "=r"(r0), "=r"(r1), "=r"(r2), "=r"(r3) : "r"(addr));
}
__device__ __forceinline__ void mma16816(float* d, const unsigned* a,
                                         unsigned b0, unsigned b1) {
    asm volatile("mma.sync.aligned.m16n8k16.row.col.f32.bf16.bf16.f32 "
                 "{%0,%1,%2,%3}, {%4,%5,%6,%7}, {%8,%9}, {%0,%1,%2,%3};"
                 : "+f"(d[0]), "+f"(d[1]), "+f"(d[2]), "+f"(d[3])
                 : "r"(a[0]), "r"(a[1]), "r"(a[2]), "r"(a[3]), "r"(b0), "r"(b1));
}

__device__ __forceinline__ void k3_stage(unsigned su, int tile, int t,
                                         const float* __restrict__ x) {
    int b = tile >> 10;
    int p0 = (tile & 1023) * 64;
    #pragma unroll
    for (int rep = 0; rep < 4; rep++) {
        int idx = t + rep*256;
        int cc = idx >> 3, q = idx & 7;
        size_t gi = ((size_t)(b*C + cc))*HW + p0 + q*8;
        unsigned doff = cc*(SB_STRIDE*2) + q*16;
        cpa16(su + doff, g_h + gi);
        cpa16(su + SB_BYTES + doff, g_v + gi);
    }
    #pragma unroll
    for (int rep = 0; rep < 8; rep++) {
        int idx = t + rep*256;
        int cc = idx >> 4, q = idx & 15;
        size_t gi = ((size_t)(b*C + cc))*HW + p0 + q*4;
        cpa16(su + 2*SB_BYTES + cc*(SX_STRIDE*4) + q*16, x + gi);
    }
}

__global__ void __launch_bounds__(256, 1) k3_fuse(const float* __restrict__ x,
                                                  const float* __restrict__ fb,
                                                  float* __restrict__ out) {
    extern __shared__ __align__(16) char sm3[];
    unsigned st0u = (unsigned)__cvta_generic_to_shared(sm3);
    unsigned st1u = st0u + STAGE_BYTES;
    int t = threadIdx.x;
    int w = t >> 5, l = t & 31;
    int wm = w >> 1, wn = w & 1;          // 4 M-warps x 2 N-warps

    int bRowLocal = (l & 7) + (((l >> 3) & 1) << 3);
    int colHalf = (l >> 4) * 8;

    // ---- prologue: stage fw into buf0, hoist A fragments (2 m-frags/warp) ----
    #pragma unroll
    for (int rep = 0; rep < 8; rep++) {
        int idx = t + rep*256;
        int row = idx >> 4, cq = idx & 15;
        cpa16(st0u + row*(SFW_STRIDE*2) + cq*16, g_fwb + row*128 + cq*8);
    }
    asm volatile("cp.async.commit_group;");
    asm volatile("cp.async.wait_group 0;");
    __syncthreads();
    unsigned afr[8][2][4];
    #pragma unroll
    for (int kk = 0; kk < 8; kk++)
        #pragma unroll
        for (int mf = 0; mf < 2; mf++) {
            int aRow = wm*32 + mf*16 + (l & 15);
            unsigned aAddr = st0u + (unsigned)(aRow*SFW_STRIDE + kk*16 + colHalf)*2u;
            ldsm_x4(aAddr, afr[kk][mf][0], afr[kk][mf][1],
                           afr[kk][mf][2], afr[kk][mf][3]);
        }
    __syncthreads();   // all warps done with fw region before overwrite

    int tile = blockIdx.x;
    if (tile < NTILES) k3_stage(st0u, tile, t, x);
    asm volatile("cp.async.commit_group;");
    if (tile + NB3 < NTILES) k3_stage(st1u, tile + NB3, t, x);
    asm volatile("cp.async.commit_group;");

    float fbv[2][2];
    #pragma unroll
    for (int mf = 0; mf < 2; mf++) {
        int r0 = wm*32 + mf*16 + (l >> 2);
        fbv[mf][0] = fb[r0];
        fbv[mf][1] = fb[r0 + 8];
    }

    for (int it = 0; tile < NTILES; tile += NB3, it++) {
        unsigned cur = (it & 1) ? st1u : st0u;
        asm volatile("cp.async.wait_group 1;");
        __syncthreads();

        int b = tile >> 10;
        int p0 = (tile & 1023) * 64;
        float wh = g_gate[b*2 + 0], wv = g_gate[b*2 + 1];
        unsigned sHu = cur, sVu = cur + SB_BYTES;
        const char* sX = sm3 + (cur - st0u) + 2*SB_BYTES;

        // acc[mf][nf][4] for H and V; nf indexes two 16-px blocks -> 2 n8 frags each
        float accH[2][4][4], accV[2][4][4];
        #pragma unroll
        for (int mf = 0; mf < 2; mf++)
            #pragma unroll
            for (int nf = 0; nf < 4; nf++)
                #pragma unroll
                for (int i = 0; i < 4; i++) { accH[mf][nf][i] = 0.f; accV[mf][nf][i] = 0.f; }

        #pragma unroll
        for (int kk = 0; kk < 8; kk++) {
            #pragma unroll
            for (int nn = 0; nn < 2; nn++) {
                unsigned boff = (unsigned)((kk*16 + bRowLocal)*SB_STRIDE
                                           + wn*32 + nn*16 + colHalf)*2u;
                unsigned b0, b1, b2, b3;
                ldsm_x4t(sHu + boff, b0, b1, b2, b3);
                #pragma unroll
                for (int mf = 0; mf < 2; mf++) {
                    mma16816(accH[mf][2*nn],     afr[kk][mf], b0, b1);
                    mma16816(accH[mf][2*nn + 1], afr[kk][mf], b2, b3);
                }
                ldsm_x4t(sVu + boff, b0, b1, b2, b3);
                #pragma unroll
                for (int mf = 0; mf < 2; mf++) {
                    mma16816(accV[mf][2*nn],     afr[kk][mf], b0, b1);
                    mma16816(accV[mf][2*nn + 1], afr[kk][mf], b2, b3);
                }
            }
        }

        int pxl = wn*32 + 2*(l & 3);
        #pragma unroll
        for (int mf = 0; mf < 2; mf++) {
            int r0 = wm*32 + mf*16 + (l >> 2);
            float fb0 = fbv[mf][0], fb1 = fbv[mf][1];
            #pragma unroll
            for (int nf = 0; nf < 4; nf++) {
                int px = pxl + nf*8;
                float2 xv0 = *(const float2*)(sX + r0*(SX_STRIDE*4) + px*4);
                float a0 = fmaf(wh, accH[mf][nf][0], wv * accV[mf][nf][0]);
                float a1 = fmaf(wh, accH[mf][nf][1], wv * accV[mf][nf][1]);
                float2 o0;
                o0.x = xv0.x * (0.5f + 0.5f*(a0 + fb0));
                o0.y = xv0.y * (0.5f + 0.5f*(a1 + fb0));
                size_t base0 = ((size_t)(b*C + r0))*HW + p0 + px;
                *(float2*)(out + base0) = o0;
                float2 xv1 = *(const float2*)(sX + (r0 + 8)*(SX_STRIDE*4) + px*4);
                float a2 = fmaf(wh, accH[mf][nf][2], wv * accV[mf][nf][2]);
                float a3 = fmaf(wh, accH[mf][nf][3], wv * accV[mf][nf][3]);
                float2 o1;
                o1.x = xv1.x * (0.5f + 0.5f*(a2 + fb1));
                o1.y = xv1.y * (0.5f + 0.5f*(a3 + fb1));
                *(float2*)(out + base0 + (size_t)8*HW) = o1;
            }
        }
        __syncthreads();

        int stile = tile + 2*NB3;
        if (stile < NTILES) k3_stage(cur, stile, t, x);
        asm volatile("cp.async.commit_group;");
    }
}

// ---------------- launch -------------------------------------------------------------
extern "C" void kernel_launch(void* const* d_in, const int* in_sizes, int n_in,
                              void* d_out, int out_size) {
    const float* x   = (const float*)d_in[0];
    const float* h1  = (const float*)d_in[1];
    const float* h2  = (const float*)d_in[2];
    const float* v1  = (const float*)d_in[3];
    const float* v2  = (const float*)d_in[4];
    const float* g1  = (const float*)d_in[5];
    const float* g2  = (const float*)d_in[6];
    const float* g2b = (const float*)d_in[7];
    const float* fw  = (const float*)d_in[8];
    const float* fb  = (const float*)d_in[9];
    float* out = (float*)d_out;

    static int smem_set = 0;
    if (!smem_set) {
        cudaFuncSetAttribute(k3_fuse, cudaFuncAttributeMaxDynamicSharedMemorySize,
                             K3_SMEM);
        smem_set = 1;
    }

    k1_conv<<<GRID_K1, 256>>>(x, h1, h2, v1, v2);
    k2_gate<<<1, 512>>>(g1, g2, g2b, fw);
    k3_fuse<<<NB3, 256, K3_SMEM>>>(x, fb, out);
}